// round 9
// baseline (speedup 1.0000x reference)
#include <cuda_runtime.h>
#include <cstdint>
#include <math_constants.h>

#define NN 100000
#define NE 1600000
#define MSORT 131072   // next pow2 >= NN
#define SCB 1024
#define NB  ((NN + SCB - 1) / SCB)   // 98

// ---------------- scratch (static device globals; no allocations) ----------
__device__ float g_tmp [NN*64];
__device__ float g_bufA[NN*64];
__device__ float g_bufB[NN*64];
__device__ float g_h1  [NN*64];
__device__ float g_h2  [NN*64];
__device__ float g_c1  [NN*64];
__device__ float g_dinv[NN];
__device__ int   g_deg [NN];
__device__ int   g_fill[NN];
__device__ int   g_rowptr[NN+1];
__device__ int   g_part[NB+1];
__device__ int   g_col [NE];
__device__ float g_wgt [NE];
__device__ float g_key [MSORT];
__device__ int   g_sidx[MSORT];
__device__ float g_w1t [5*64*64];
__device__ float g_w2t [5*64*64];

// ---------------- f32x2 packed helpers --------------------------------------
typedef unsigned long long u64;
__device__ __forceinline__ u64 pk2(float a, float b)
{
    u64 r; asm("mov.b64 %0, {%1, %2};" : "=l"(r) : "f"(a), "f"(b)); return r;
}
__device__ __forceinline__ u64 dup2(float a) { return pk2(a, a); }
__device__ __forceinline__ void fma2(u64& d, u64 a, u64 b)
{
    asm("fma.rn.f32x2 %0, %1, %2, %0;" : "+l"(d) : "l"(a), "l"(b));
}
__device__ __forceinline__ float2 up2(u64 v)
{
    float2 f; asm("mov.b64 {%0, %1}, %2;" : "=f"(f.x), "=f"(f.y) : "l"(v)); return f;
}

// ---------------- init: zero degrees + pad sort keys -------------------------
__global__ void k_init()
{
    int i = blockIdx.x*blockDim.x + threadIdx.x;
    if (i < NN) g_deg[i] = 0;
    if (i >= NN && i < MSORT) { g_key[i] = CUDART_INF_F; g_sidx[i] = i; }
}

__global__ void k_deg(const int* __restrict__ dst)
{
    int e = blockIdx.x*blockDim.x + threadIdx.x;
    if (e < NE) atomicAdd(&g_deg[dst[e]], 1);
}

__global__ void k_scan1()
{
    __shared__ int s[SCB];
    int b = blockIdx.x, t = threadIdx.x;
    int i = b*SCB + t;
    int v = (i < NN) ? g_deg[i] : 0;
    s[t] = v;
    __syncthreads();
#pragma unroll
    for (int off = 1; off < SCB; off <<= 1) {
        int u = (t >= off) ? s[t - off] : 0;
        __syncthreads();
        s[t] += u;
        __syncthreads();
    }
    if (i < NN) g_rowptr[i] = s[t];
    if (t == SCB-1) g_part[b] = s[SCB-1];
}

__global__ void k_scan2()
{
    __shared__ int s[128];
    int t = threadIdx.x;
    int v = (t < NB) ? g_part[t] : 0;
    s[t] = v;
    __syncthreads();
#pragma unroll
    for (int off = 1; off < 128; off <<= 1) {
        int u = (t >= off) ? s[t - off] : 0;
        __syncthreads();
        s[t] += u;
        __syncthreads();
    }
    if (t < NB) g_part[t] = s[t] - v;
}

__global__ void k_scan3()
{
    int b = blockIdx.x, t = threadIdx.x;
    int i = b*SCB + t;
    if (i < NN) {
        int d = g_deg[i];
        g_rowptr[i] = g_rowptr[i] + g_part[b] - d;   // exclusive
        g_fill[i] = 0;
        g_dinv[i] = rsqrtf((float)(d + 1));          // +1 self loop
    }
    if (b == 0 && t == 0) g_rowptr[NN] = NE;
}

__global__ void k_fill(const int* __restrict__ src, const int* __restrict__ dst)
{
    int e = blockIdx.x*blockDim.x + threadIdx.x;
    if (e >= NE) return;
    int d = dst[e], s = src[e];
    int p = g_rowptr[d] + atomicAdd(&g_fill[d], 1);
    g_col[p] = s;
    g_wgt[p] = g_dinv[s] * g_dinv[d];
}

// ---------------- GEMM: C[n,64] = A[n,CI] @ W[CI,64] -------------------------
// 128-row tile, 128 threads (8,16), 8x8 per-thread microtile.
__global__ void __launch_bounds__(128) k_gemm(
    const float* __restrict__ A, int CI,
    const float* __restrict__ W,
    float* __restrict__ C, int n)
{
    __shared__ float As[128][64];   // [row][k]
    __shared__ float Ws[64][64];    // [k][col]
    int tx = threadIdx.x;           // 0..7  -> cols tx*8..+7
    int ty = threadIdx.y;           // 0..15 -> rows ty*8..+7
    int tid = ty*8 + tx;
    int r0 = blockIdx.x * 128;
    u64 acc[8][4] = {};
    int ntiles = CI >> 6;
    for (int kt = 0; kt < ntiles; ++kt) {
        __syncthreads();
        for (int idx = tid; idx < 128*64; idx += 128) {
            int row = idx >> 6, k = idx & 63;
            int gr = r0 + row;
            As[row][k] = (gr < n) ? A[(size_t)gr*CI + kt*64 + k] : 0.f;
        }
        for (int idx = tid; idx < 64*64; idx += 128) {
            int kr = idx >> 6, c = idx & 63;
            Ws[kr][c] = W[(size_t)(kt*64 + kr)*64 + c];
        }
        __syncthreads();
#pragma unroll 2
        for (int k4 = 0; k4 < 64; k4 += 4) {
            float4 av[8];
#pragma unroll
            for (int i = 0; i < 8; ++i)
                av[i] = *reinterpret_cast<const float4*>(&As[ty*8+i][k4]);
            const float* af = reinterpret_cast<const float*>(av);
#pragma unroll
            for (int kk = 0; kk < 4; ++kk) {
                ulonglong2 wA = *reinterpret_cast<const ulonglong2*>(&Ws[k4+kk][tx*8]);
                ulonglong2 wB = *reinterpret_cast<const ulonglong2*>(&Ws[k4+kk][tx*8+4]);
#pragma unroll
                for (int i = 0; i < 8; ++i) {
                    u64 ai = dup2(af[i*4 + kk]);
                    fma2(acc[i][0], ai, wA.x); fma2(acc[i][1], ai, wA.y);
                    fma2(acc[i][2], ai, wB.x); fma2(acc[i][3], ai, wB.y);
                }
            }
        }
    }
#pragma unroll
    for (int i = 0; i < 8; ++i) {
        int gr = r0 + ty*8 + i;
        if (gr < n) {
            float2 p0 = up2(acc[i][0]), p1 = up2(acc[i][1]);
            float2 p2 = up2(acc[i][2]), p3 = up2(acc[i][3]);
            *reinterpret_cast<float4*>(&C[(size_t)gr*64 + tx*8])     = make_float4(p0.x,p0.y,p1.x,p1.y);
            *reinterpret_cast<float4*>(&C[(size_t)gr*64 + tx*8 + 4]) = make_float4(p2.x,p2.y,p3.x,p3.y);
        }
    }
}

// ---------------- GCN aggregation (warp per node, float2 lanes) --------------
__global__ void k_agg(const float* __restrict__ T, const float* __restrict__ b,
                      float* __restrict__ O, int relu, int n,
                      const float* __restrict__ score_w, const float* __restrict__ score_b)
{
    int w    = (blockIdx.x*blockDim.x + threadIdx.x) >> 5;
    int lane = threadIdx.x & 31;
    if (w >= n) return;
    const float2* T2 = reinterpret_cast<const float2*>(T);
    int s = g_rowptr[w], e = g_rowptr[w+1];
    float a0 = 0.f, a1 = 0.f;
    int j = s;
    for (; j + 4 <= e; j += 4) {
        int   c0 = g_col[j],  c1 = g_col[j+1],  c2 = g_col[j+2],  c3 = g_col[j+3];
        float w0 = g_wgt[j],  w1 = g_wgt[j+1],  w2 = g_wgt[j+2],  w3 = g_wgt[j+3];
        float2 t0 = T2[(size_t)c0*32 + lane];
        float2 t1 = T2[(size_t)c1*32 + lane];
        float2 t2 = T2[(size_t)c2*32 + lane];
        float2 t3 = T2[(size_t)c3*32 + lane];
        a0 += w0*t0.x + w1*t1.x + w2*t2.x + w3*t3.x;
        a1 += w0*t0.y + w1*t1.y + w2*t2.y + w3*t3.y;
    }
    for (; j < e; ++j) {
        int c = g_col[j]; float ww = g_wgt[j];
        float2 t = T2[(size_t)c*32 + lane];
        a0 += ww * t.x;
        a1 += ww * t.y;
    }
    float di = g_dinv[w]; float sw = di*di;
    float2 ts = T2[(size_t)w*32 + lane];
    a0 += sw * ts.x;
    a1 += sw * ts.y;
    float2 bb = reinterpret_cast<const float2*>(b)[lane];
    a0 += bb.x;
    a1 += bb.y;
    if (relu) { a0 = fmaxf(a0, 0.f); a1 = fmaxf(a1, 0.f); }
    reinterpret_cast<float2*>(O)[(size_t)w*32 + lane] = make_float2(a0, a1);
    if (score_w) {
        float2 wp = reinterpret_cast<const float2*>(score_w)[lane];
        float p = a0*wp.x + a1*wp.y;
#pragma unroll
        for (int o = 16; o; o >>= 1) p += __shfl_xor_sync(0xffffffffu, p, o);
        if (lane == 0) { g_key[w] = p + score_b[0]; g_sidx[w] = w; }
    }
}

// ---------------- bitonic sort (stable via index tie-break) ------------------
__device__ __forceinline__ bool cmp_gt(float ka, int ia, float kb, int ib)
{
    return (ka > kb) || (ka == kb && ia > ib);
}
__device__ __forceinline__ void ce(float& ka, int& ia, float& kb, int& ib, bool asc)
{
    if (cmp_gt(ka, ia, kb, ib) == asc) {
        float tk = ka; ka = kb; kb = tk;
        int   ti = ia; ia = ib; ib = ti;
    }
}

__global__ void k_localsort()
{
    __shared__ float sk[2048];
    __shared__ int   si[2048];
    int t = threadIdx.x;
    int base = blockIdx.x * 2048;
    sk[t]        = g_key[base + t];        si[t]        = g_sidx[base + t];
    sk[t + 1024] = g_key[base + t + 1024]; si[t + 1024] = g_sidx[base + t + 1024];
    for (int k = 2; k <= 2048; k <<= 1) {
        for (int j = k >> 1; j > 0; j >>= 1) {
            __syncthreads();
            int i = ((t & ~(j-1)) << 1) | (t & (j-1));
            int p = i + j;
            bool asc = (((base + i) & k) == 0);
            float ki = sk[i], kp = sk[p];
            int   xi = si[i], xp = si[p];
            if (cmp_gt(ki, xi, kp, xp) == asc) {
                sk[i] = kp; sk[p] = ki; si[i] = xp; si[p] = xi;
            }
        }
    }
    __syncthreads();
    g_key[base + t]        = sk[t];        g_sidx[base + t]        = si[t];
    g_key[base + t + 1024] = sk[t + 1024]; g_sidx[base + t + 1024] = si[t + 1024];
}

__global__ void k_gp1(int k, int j)
{
    int t = blockIdx.x*blockDim.x + threadIdx.x;   // < MSORT/2
    int i = ((t & ~(j-1)) << 1) | (t & (j-1));
    int p = i + j;
    bool asc = ((i & k) == 0);
    float ki = g_key[i], kp = g_key[p];
    int   xi = g_sidx[i], xp = g_sidx[p];
    if (cmp_gt(ki, xi, kp, xp) == asc) {
        g_key[i] = kp; g_key[p] = ki; g_sidx[i] = xp; g_sidx[p] = xi;
    }
}

__global__ void k_gp2(int k, int j)
{
    int t = blockIdx.x*blockDim.x + threadIdx.x;   // < MSORT/4
    int q = j >> 1;
    int i0 = ((t & ~(q-1)) << 2) | (t & (q-1));
    float kk[4]; int xx[4];
#pragma unroll
    for (int m = 0; m < 4; ++m) { kk[m] = g_key[i0 + m*q]; xx[m] = g_sidx[i0 + m*q]; }
    bool asc = ((i0 & k) == 0);
    ce(kk[0],xx[0],kk[2],xx[2],asc); ce(kk[1],xx[1],kk[3],xx[3],asc);
    ce(kk[0],xx[0],kk[1],xx[1],asc); ce(kk[2],xx[2],kk[3],xx[3],asc);
#pragma unroll
    for (int m = 0; m < 4; ++m) { g_key[i0 + m*q] = kk[m]; g_sidx[i0 + m*q] = xx[m]; }
}

__global__ void k_gp3(int k, int j)
{
    int t = blockIdx.x*blockDim.x + threadIdx.x;   // < MSORT/8
    int q = j >> 2;
    int i0 = ((t & ~(q-1)) << 3) | (t & (q-1));
    float kk[8]; int xx[8];
#pragma unroll
    for (int m = 0; m < 8; ++m) { kk[m] = g_key[i0 + m*q]; xx[m] = g_sidx[i0 + m*q]; }
    bool asc = ((i0 & k) == 0);
#pragma unroll
    for (int m = 0; m < 4; ++m) ce(kk[m],xx[m],kk[m+4],xx[m+4],asc);
    ce(kk[0],xx[0],kk[2],xx[2],asc); ce(kk[1],xx[1],kk[3],xx[3],asc);
    ce(kk[4],xx[4],kk[6],xx[6],asc); ce(kk[5],xx[5],kk[7],xx[7],asc);
    ce(kk[0],xx[0],kk[1],xx[1],asc); ce(kk[2],xx[2],kk[3],xx[3],asc);
    ce(kk[4],xx[4],kk[5],xx[5],asc); ce(kk[6],xx[6],kk[7],xx[7],asc);
#pragma unroll
    for (int m = 0; m < 8; ++m) { g_key[i0 + m*q] = kk[m]; g_sidx[i0 + m*q] = xx[m]; }
}

__global__ void k_mergeshared(int k)
{
    __shared__ float sk[2048];
    __shared__ int   si[2048];
    int t = threadIdx.x;
    int base = blockIdx.x * 2048;
    sk[t]        = g_key[base + t];        si[t]        = g_sidx[base + t];
    sk[t + 1024] = g_key[base + t + 1024]; si[t + 1024] = g_sidx[base + t + 1024];
    bool asc = ((base & k) == 0);
    for (int j = 1024; j > 0; j >>= 1) {
        __syncthreads();
        int i = ((t & ~(j-1)) << 1) | (t & (j-1));
        int p = i + j;
        float ki = sk[i], kp = sk[p];
        int   xi = si[i], xp = si[p];
        if (cmp_gt(ki, xi, kp, xp) == asc) {
            sk[i] = kp; sk[p] = ki; si[i] = xp; si[p] = xi;
        }
    }
    __syncthreads();
    g_key[base + t]        = sk[t];        g_sidx[base + t]        = si[t];
    g_key[base + t + 1024] = sk[t + 1024]; g_sidx[base + t + 1024] = si[t + 1024];
}

// ---------------- conv weight transpose: [co][ci][k] -> [k][ci][co] ----------
__global__ void k_transw(const float* __restrict__ w1, const float* __restrict__ w2)
{
    int t = blockIdx.x*blockDim.x + threadIdx.x;
    if (t >= 2*5*64*64) return;
    int which = t >= 5*64*64;
    int u = t - which*5*64*64;
    int co = u & 63;
    int ci = (u >> 6) & 63;
    int kk = u >> 12;
    float v = which ? w2[co*320 + ci*5 + kk] : w1[co*320 + ci*5 + kk];
    if (which) g_w2t[u] = v; else g_w1t[u] = v;
}

// ---------------- conv1d over ranks (K=5, pad=2, 8x8 microtile) --------------
// 128-row tile + 4-row halo; per-tap weight reload (16KB).
// gather=1: input row r is g_key[r] * g_h1[g_sidx[r]][ci]  (fused buildsx)
__global__ void __launch_bounds__(128) k_conv(
    const float* __restrict__ X, const float* __restrict__ Wt,
    const float* __restrict__ b, float* __restrict__ Y,
    const int* __restrict__ scat, int relu, int gather, int n)
{
    extern __shared__ float cs[];
    float (*xs)[64] = reinterpret_cast<float(*)[64]>(cs);           // [132][64]
    float (*ws)[64] = reinterpret_cast<float(*)[64]>(cs + 132*64);  // [64][64]
    int tx = threadIdx.x;           // 0..7
    int ty = threadIdx.y;           // 0..15
    int tid = ty*8 + tx;
    int r0 = blockIdx.x * 128;
    for (int idx = tid; idx < 132*64; idx += 128) {
        int rl = idx >> 6, ci = idx & 63;
        int r = r0 - 2 + rl;
        float v = 0.f;
        if (r >= 0 && r < n) {
            if (gather) v = g_key[r] * g_h1[(size_t)g_sidx[r]*64 + ci];
            else        v = X[(size_t)r*64 + ci];
        }
        xs[rl][ci] = v;
    }
    u64 acc[8][4] = {};
    for (int k = 0; k < 5; ++k) {
        __syncthreads();
        for (int idx = tid; idx < 4096; idx += 128)
            ws[idx >> 6][idx & 63] = Wt[k*4096 + idx];
        __syncthreads();
#pragma unroll 2
        for (int c4 = 0; c4 < 64; c4 += 4) {
            float4 av[8];
#pragma unroll
            for (int i = 0; i < 8; ++i)
                av[i] = *reinterpret_cast<const float4*>(&xs[ty*8+i+k][c4]);
            const float* af = reinterpret_cast<const float*>(av);
#pragma unroll
            for (int cc = 0; cc < 4; ++cc) {
                ulonglong2 wA = *reinterpret_cast<const ulonglong2*>(&ws[c4+cc][tx*8]);
                ulonglong2 wB = *reinterpret_cast<const ulonglong2*>(&ws[c4+cc][tx*8+4]);
#pragma unroll
                for (int i = 0; i < 8; ++i) {
                    u64 ai = dup2(af[i*4 + cc]);
                    fma2(acc[i][0], ai, wA.x); fma2(acc[i][1], ai, wA.y);
                    fma2(acc[i][2], ai, wB.x); fma2(acc[i][3], ai, wB.y);
                }
            }
        }
    }
#pragma unroll
    for (int i = 0; i < 8; ++i) {
        int r = r0 + ty*8 + i;
        if (r < n) {
            int orow = scat ? scat[r] : r;
            float2 p0 = up2(acc[i][0]), p1 = up2(acc[i][1]);
            float2 p2 = up2(acc[i][2]), p3 = up2(acc[i][3]);
            float4 o1 = make_float4(p0.x + b[tx*8+0], p0.y + b[tx*8+1],
                                    p1.x + b[tx*8+2], p1.y + b[tx*8+3]);
            float4 o2 = make_float4(p2.x + b[tx*8+4], p2.y + b[tx*8+5],
                                    p3.x + b[tx*8+6], p3.y + b[tx*8+7]);
            if (relu) {
                o1.x = fmaxf(o1.x, 0.f); o1.y = fmaxf(o1.y, 0.f);
                o1.z = fmaxf(o1.z, 0.f); o1.w = fmaxf(o1.w, 0.f);
                o2.x = fmaxf(o2.x, 0.f); o2.y = fmaxf(o2.y, 0.f);
                o2.z = fmaxf(o2.z, 0.f); o2.w = fmaxf(o2.w, 0.f);
            }
            *reinterpret_cast<float4*>(&Y[(size_t)orow*64 + tx*8])     = o1;
            *reinterpret_cast<float4*>(&Y[(size_t)orow*64 + tx*8 + 4]) = o2;
        }
    }
}

// ---------------- final linear: out = [h1|h2] @ lin_w + lin_b ----------------
__global__ void __launch_bounds__(128) k_lin(
    const float* __restrict__ A0, const float* __restrict__ A1,
    const float* __restrict__ W, const float* __restrict__ b,
    float* __restrict__ C, int n)
{
    __shared__ float As[128][64];
    __shared__ float Ws[64][64];
    int tx = threadIdx.x;
    int ty = threadIdx.y;
    int tid = ty*8 + tx;
    int r0 = blockIdx.x * 128;
    u64 acc[8][4] = {};
    for (int kt = 0; kt < 2; ++kt) {
        const float* A = (kt == 0) ? A0 : A1;
        __syncthreads();
        for (int idx = tid; idx < 128*64; idx += 128) {
            int row = idx >> 6, k = idx & 63;
            int gr = r0 + row;
            As[row][k] = (gr < n) ? A[(size_t)gr*64 + k] : 0.f;
        }
        for (int idx = tid; idx < 64*64; idx += 128) {
            int kr = idx >> 6, c = idx & 63;
            Ws[kr][c] = W[(size_t)(kt*64 + kr)*64 + c];
        }
        __syncthreads();
#pragma unroll 2
        for (int k4 = 0; k4 < 64; k4 += 4) {
            float4 av[8];
#pragma unroll
            for (int i = 0; i < 8; ++i)
                av[i] = *reinterpret_cast<const float4*>(&As[ty*8+i][k4]);
            const float* af = reinterpret_cast<const float*>(av);
#pragma unroll
            for (int kk = 0; kk < 4; ++kk) {
                ulonglong2 wA = *reinterpret_cast<const ulonglong2*>(&Ws[k4+kk][tx*8]);
                ulonglong2 wB = *reinterpret_cast<const ulonglong2*>(&Ws[k4+kk][tx*8+4]);
#pragma unroll
                for (int i = 0; i < 8; ++i) {
                    u64 ai = dup2(af[i*4 + kk]);
                    fma2(acc[i][0], ai, wA.x); fma2(acc[i][1], ai, wA.y);
                    fma2(acc[i][2], ai, wB.x); fma2(acc[i][3], ai, wB.y);
                }
            }
        }
    }
#pragma unroll
    for (int i = 0; i < 8; ++i) {
        int gr = r0 + ty*8 + i;
        if (gr < n) {
            float2 p0 = up2(acc[i][0]), p1 = up2(acc[i][1]);
            float2 p2 = up2(acc[i][2]), p3 = up2(acc[i][3]);
            float4 o1 = make_float4(p0.x + b[tx*8+0], p0.y + b[tx*8+1],
                                    p1.x + b[tx*8+2], p1.y + b[tx*8+3]);
            float4 o2 = make_float4(p2.x + b[tx*8+4], p2.y + b[tx*8+5],
                                    p3.x + b[tx*8+6], p3.y + b[tx*8+7]);
            *reinterpret_cast<float4*>(&C[(size_t)gr*64 + tx*8])     = o1;
            *reinterpret_cast<float4*>(&C[(size_t)gr*64 + tx*8 + 4]) = o2;
        }
    }
}

// ---------------- host launcher ---------------------------------------------
extern "C" void kernel_launch(void* const* d_in, const int* in_sizes, int n_in,
                              void* d_out, int out_size)
{
    const float* x   = (const float*)d_in[0];
    const int*   ei  = (const int*)  d_in[1];
    const float* W0  = (const float*)d_in[2];
    const float* b0  = (const float*)d_in[3];
    const float* W1  = (const float*)d_in[4];
    const float* b1  = (const float*)d_in[5];
    const float* W2  = (const float*)d_in[6];
    const float* b2  = (const float*)d_in[7];
    const float* Wp  = (const float*)d_in[8];
    const float* bp  = (const float*)d_in[9];
    const float* c1w = (const float*)d_in[10];
    const float* c1b = (const float*)d_in[11];
    const float* c2w = (const float*)d_in[12];
    const float* c2b = (const float*)d_in[13];
    const float* lw  = (const float*)d_in[14];
    const float* lb  = (const float*)d_in[15];
    float* out = (float*)d_out;

    const int n = NN, E = NE;
    const int* src = ei;
    const int* dst = ei + E;

    float *p_tmp, *p_bufA, *p_bufB, *p_h1, *p_h2, *p_c1, *p_w1t, *p_w2t;
    int *p_sidx;
    cudaGetSymbolAddress((void**)&p_tmp,  g_tmp);
    cudaGetSymbolAddress((void**)&p_bufA, g_bufA);
    cudaGetSymbolAddress((void**)&p_bufB, g_bufB);
    cudaGetSymbolAddress((void**)&p_h1,   g_h1);
    cudaGetSymbolAddress((void**)&p_h2,   g_h2);
    cudaGetSymbolAddress((void**)&p_c1,   g_c1);
    cudaGetSymbolAddress((void**)&p_w1t,  g_w1t);
    cudaGetSymbolAddress((void**)&p_w2t,  g_w2t);
    cudaGetSymbolAddress((void**)&p_sidx, g_sidx);

    const int CONV_SMEM = (132*64 + 64*64) * 4;   // 50,176 B
    cudaFuncSetAttribute(k_conv, cudaFuncAttributeMaxDynamicSharedMemorySize, CONV_SMEM);

    dim3 tg8(8, 16);
    int  gb  = (n + 127) / 128;
    int  ab  = (n + 7) / 8;     // warp per node, 8 warps/block

    // ---- CSR build; layer-0 gemm kept as 4th launch (stable ncu slot) ----
    k_init <<<(MSORT + 255)/256, 256>>>();
    k_deg  <<<(E + 255)/256, 256>>>(dst);
    k_scan1<<<NB, SCB>>>();
    k_gemm <<<gb, tg8>>>(x, 128, W0, p_tmp, n);          // <-- profile target
    k_scan2<<<1, 128>>>();
    k_scan3<<<NB, SCB>>>();
    k_fill <<<(E + 255)/256, 256>>>(src, dst);

    // ---- 3 GCN layers (layer 3 fuses the score projection) ----
    k_agg <<<ab, 256>>>(p_tmp, b0, p_bufA, 1, n, nullptr, nullptr);
    k_gemm<<<gb, tg8>>>(p_bufA, 64, W1, p_tmp, n);
    k_agg <<<ab, 256>>>(p_tmp, b1, p_bufB, 1, n, nullptr, nullptr);
    k_gemm<<<gb, tg8>>>(p_bufB, 64, W2, p_tmp, n);
    k_agg <<<ab, 256>>>(p_tmp, b2, p_h1, 0, n, Wp, bp);

    // ---- stable bitonic argsort (fused global steps) ----
    k_localsort<<<MSORT/2048, 1024>>>();
    for (int k = 4096; k <= MSORT; k <<= 1) {
        int j = k >> 1;
        while (j >= 2048) {
            if (j >= 8192)      { k_gp3<<<MSORT/8/256, 256>>>(k, j); j >>= 3; }
            else if (j >= 4096) { k_gp2<<<MSORT/4/256, 256>>>(k, j); j >>= 2; }
            else                { k_gp1<<<MSORT/2/256, 256>>>(k, j); j >>= 1; }
        }
        k_mergeshared<<<MSORT/2048, 1024>>>(k);
    }

    // ---- convs (conv1 gathers sorted_x on the fly, conv2 scatters back),
    //      final linear ----
    k_transw<<<(2*5*64*64 + 255)/256, 256>>>(c1w, c2w);
    k_conv<<<gb, tg8, CONV_SMEM>>>(nullptr, p_w1t, c1b, p_c1, nullptr, 1, 1, n);
    k_conv<<<gb, tg8, CONV_SMEM>>>(p_c1,    p_w2t, c2b, p_h2, p_sidx, 0, 0, n);
    k_lin<<<gb, tg8>>>(p_h1, p_h2, lw, lb, out, n);
}

// round 15
// speedup vs baseline: 1.1305x; 1.1305x over previous
#include <cuda_runtime.h>
#include <cstdint>
#include <math_constants.h>

#define NN 100000
#define NE 1600000
#define MSORT 131072   // next pow2 >= NN
#define SCB 1024
#define NB  ((NN + SCB - 1) / SCB)   // 98

// ---------------- scratch (static device globals; no allocations) ----------
__device__ float g_tmp [NN*64];
__device__ float g_bufA[NN*64];
__device__ float g_bufB[NN*64];
__device__ float g_h1  [NN*64];
__device__ float g_h2  [NN*64];
__device__ float g_c1  [NN*64];
__device__ float g_dinv[NN];
__device__ int   g_deg [NN];
__device__ int   g_fill[NN];
__device__ int   g_rowptr[NN+1];
__device__ int   g_part[NB+1];
__device__ int   g_col [NE];
__device__ float g_wgt [NE];
__device__ float g_key [MSORT];
__device__ int   g_sidx[MSORT];
__device__ float g_w1t [5*64*64];
__device__ float g_w2t [5*64*64];

// ---------------- f32x2 packed helpers --------------------------------------
typedef unsigned long long u64;
__device__ __forceinline__ u64 pk2(float a, float b)
{
    u64 r; asm("mov.b64 %0, {%1, %2};" : "=l"(r) : "f"(a), "f"(b)); return r;
}
__device__ __forceinline__ u64 dup2(float a) { return pk2(a, a); }
__device__ __forceinline__ void fma2(u64& d, u64 a, u64 b)
{
    asm("fma.rn.f32x2 %0, %1, %2, %0;" : "+l"(d) : "l"(a), "l"(b));
}
__device__ __forceinline__ float2 up2(u64 v)
{
    float2 f; asm("mov.b64 {%0, %1}, %2;" : "=f"(f.x), "=f"(f.y) : "l"(v)); return f;
}

// ---------------- init: zero degrees + pad sort keys -------------------------
__global__ void k_init()
{
    int i = blockIdx.x*blockDim.x + threadIdx.x;
    if (i < NN) g_deg[i] = 0;
    if (i >= NN && i < MSORT) { g_key[i] = CUDART_INF_F; g_sidx[i] = i; }
}

__global__ void k_deg(const int* __restrict__ dst)
{
    int e = blockIdx.x*blockDim.x + threadIdx.x;
    if (e < NE) atomicAdd(&g_deg[dst[e]], 1);
}

__global__ void k_scan1()
{
    __shared__ int s[SCB];
    int b = blockIdx.x, t = threadIdx.x;
    int i = b*SCB + t;
    int v = (i < NN) ? g_deg[i] : 0;
    s[t] = v;
    __syncthreads();
#pragma unroll
    for (int off = 1; off < SCB; off <<= 1) {
        int u = (t >= off) ? s[t - off] : 0;
        __syncthreads();
        s[t] += u;
        __syncthreads();
    }
    if (i < NN) g_rowptr[i] = s[t];
    if (t == SCB-1) g_part[b] = s[SCB-1];
}

__global__ void k_scan2()
{
    __shared__ int s[128];
    int t = threadIdx.x;
    int v = (t < NB) ? g_part[t] : 0;
    s[t] = v;
    __syncthreads();
#pragma unroll
    for (int off = 1; off < 128; off <<= 1) {
        int u = (t >= off) ? s[t - off] : 0;
        __syncthreads();
        s[t] += u;
        __syncthreads();
    }
    if (t < NB) g_part[t] = s[t] - v;
}

__global__ void k_scan3()
{
    int b = blockIdx.x, t = threadIdx.x;
    int i = b*SCB + t;
    if (i < NN) {
        int d = g_deg[i];
        g_rowptr[i] = g_rowptr[i] + g_part[b] - d;   // exclusive
        g_fill[i] = 0;
        g_dinv[i] = rsqrtf((float)(d + 1));          // +1 self loop
    }
    if (b == 0 && t == 0) g_rowptr[NN] = NE;
}

__global__ void k_fill(const int* __restrict__ src, const int* __restrict__ dst)
{
    int e = blockIdx.x*blockDim.x + threadIdx.x;
    if (e >= NE) return;
    int d = dst[e], s = src[e];
    int p = g_rowptr[d] + atomicAdd(&g_fill[d], 1);
    g_col[p] = s;
    g_wgt[p] = g_dinv[s] * g_dinv[d];
}

// ---------------- GEMM: C[n,64] = A[n,CI] @ W[CI,64] -------------------------
// 128-row tile, 256 threads (16,16), 8x4 per-thread microtile.
__global__ void __launch_bounds__(256) k_gemm(
    const float* __restrict__ A, int CI,
    const float* __restrict__ W,
    float* __restrict__ C, int n)
{
    __shared__ float As[128][64];   // [row][k]
    __shared__ float Ws[64][64];    // [k][col]
    int tx = threadIdx.x;           // 0..15 -> cols tx*4..+3
    int ty = threadIdx.y;           // 0..15 -> rows ty*8..+7
    int tid = ty*16 + tx;
    int r0 = blockIdx.x * 128;
    u64 acc[8][2] = {};
    int ntiles = CI >> 6;
    for (int kt = 0; kt < ntiles; ++kt) {
        __syncthreads();
        for (int idx = tid; idx < 128*64; idx += 256) {
            int row = idx >> 6, k = idx & 63;
            int gr = r0 + row;
            As[row][k] = (gr < n) ? A[(size_t)gr*CI + kt*64 + k] : 0.f;
        }
        for (int idx = tid; idx < 64*64; idx += 256) {
            int kr = idx >> 6, c = idx & 63;
            Ws[kr][c] = W[(size_t)(kt*64 + kr)*64 + c];
        }
        __syncthreads();
#pragma unroll 2
        for (int k4 = 0; k4 < 64; k4 += 4) {
            float4 av[8];
#pragma unroll
            for (int i = 0; i < 8; ++i)
                av[i] = *reinterpret_cast<const float4*>(&As[ty*8+i][k4]);
            const float* af = reinterpret_cast<const float*>(av);
#pragma unroll
            for (int kk = 0; kk < 4; ++kk) {
                ulonglong2 w = *reinterpret_cast<const ulonglong2*>(&Ws[k4+kk][tx*4]);
#pragma unroll
                for (int i = 0; i < 8; ++i) {
                    u64 ai = dup2(af[i*4 + kk]);
                    fma2(acc[i][0], ai, w.x); fma2(acc[i][1], ai, w.y);
                }
            }
        }
    }
#pragma unroll
    for (int i = 0; i < 8; ++i) {
        int gr = r0 + ty*8 + i;
        if (gr < n) {
            float2 lo = up2(acc[i][0]), hi = up2(acc[i][1]);
            *reinterpret_cast<float4*>(&C[(size_t)gr*64 + tx*4]) =
                make_float4(lo.x, lo.y, hi.x, hi.y);
        }
    }
}

// ---------------- GCN aggregation (warp per node, float2 lanes) --------------
__global__ void k_agg(const float* __restrict__ T, const float* __restrict__ b,
                      float* __restrict__ O, int relu, int n,
                      const float* __restrict__ score_w, const float* __restrict__ score_b)
{
    int w    = (blockIdx.x*blockDim.x + threadIdx.x) >> 5;
    int lane = threadIdx.x & 31;
    if (w >= n) return;
    const float2* T2 = reinterpret_cast<const float2*>(T);
    int s = g_rowptr[w], e = g_rowptr[w+1];
    float a0 = 0.f, a1 = 0.f;
    int j = s;
    for (; j + 4 <= e; j += 4) {
        int   c0 = g_col[j],  c1 = g_col[j+1],  c2 = g_col[j+2],  c3 = g_col[j+3];
        float w0 = g_wgt[j],  w1 = g_wgt[j+1],  w2 = g_wgt[j+2],  w3 = g_wgt[j+3];
        float2 t0 = T2[(size_t)c0*32 + lane];
        float2 t1 = T2[(size_t)c1*32 + lane];
        float2 t2 = T2[(size_t)c2*32 + lane];
        float2 t3 = T2[(size_t)c3*32 + lane];
        a0 += w0*t0.x + w1*t1.x + w2*t2.x + w3*t3.x;
        a1 += w0*t0.y + w1*t1.y + w2*t2.y + w3*t3.y;
    }
    for (; j < e; ++j) {
        int c = g_col[j]; float ww = g_wgt[j];
        float2 t = T2[(size_t)c*32 + lane];
        a0 += ww * t.x;
        a1 += ww * t.y;
    }
    float di = g_dinv[w]; float sw = di*di;
    float2 ts = T2[(size_t)w*32 + lane];
    a0 += sw * ts.x;
    a1 += sw * ts.y;
    float2 bb = reinterpret_cast<const float2*>(b)[lane];
    a0 += bb.x;
    a1 += bb.y;
    if (relu) { a0 = fmaxf(a0, 0.f); a1 = fmaxf(a1, 0.f); }
    reinterpret_cast<float2*>(O)[(size_t)w*32 + lane] = make_float2(a0, a1);
    if (score_w) {
        float2 wp = reinterpret_cast<const float2*>(score_w)[lane];
        float p = a0*wp.x + a1*wp.y;
#pragma unroll
        for (int o = 16; o; o >>= 1) p += __shfl_xor_sync(0xffffffffu, p, o);
        if (lane == 0) { g_key[w] = p + score_b[0]; g_sidx[w] = w; }
    }
}

// ---------------- bitonic sort (stable via index tie-break) ------------------
__device__ __forceinline__ bool cmp_gt(float ka, int ia, float kb, int ib)
{
    return (ka > kb) || (ka == kb && ia > ib);
}
__device__ __forceinline__ void ce(float& ka, int& ia, float& kb, int& ib, bool asc)
{
    if (cmp_gt(ka, ia, kb, ib) == asc) {
        float tk = ka; ka = kb; kb = tk;
        int   ti = ia; ia = ib; ib = ti;
    }
}

__global__ void k_localsort()
{
    __shared__ float sk[2048];
    __shared__ int   si[2048];
    int t = threadIdx.x;
    int base = blockIdx.x * 2048;
    sk[t]        = g_key[base + t];        si[t]        = g_sidx[base + t];
    sk[t + 1024] = g_key[base + t + 1024]; si[t + 1024] = g_sidx[base + t + 1024];
    for (int k = 2; k <= 2048; k <<= 1) {
        for (int j = k >> 1; j > 0; j >>= 1) {
            __syncthreads();
            int i = ((t & ~(j-1)) << 1) | (t & (j-1));
            int p = i + j;
            bool asc = (((base + i) & k) == 0);
            float ki = sk[i], kp = sk[p];
            int   xi = si[i], xp = si[p];
            if (cmp_gt(ki, xi, kp, xp) == asc) {
                sk[i] = kp; sk[p] = ki; si[i] = xp; si[p] = xi;
            }
        }
    }
    __syncthreads();
    g_key[base + t]        = sk[t];        g_sidx[base + t]        = si[t];
    g_key[base + t + 1024] = sk[t + 1024]; g_sidx[base + t + 1024] = si[t + 1024];
}

__global__ void k_gp1(int k, int j)
{
    int t = blockIdx.x*blockDim.x + threadIdx.x;   // < MSORT/2
    int i = ((t & ~(j-1)) << 1) | (t & (j-1));
    int p = i + j;
    bool asc = ((i & k) == 0);
    float ki = g_key[i], kp = g_key[p];
    int   xi = g_sidx[i], xp = g_sidx[p];
    if (cmp_gt(ki, xi, kp, xp) == asc) {
        g_key[i] = kp; g_key[p] = ki; g_sidx[i] = xp; g_sidx[p] = xi;
    }
}

__global__ void k_gp2(int k, int j)
{
    int t = blockIdx.x*blockDim.x + threadIdx.x;   // < MSORT/4
    int q = j >> 1;
    int i0 = ((t & ~(q-1)) << 2) | (t & (q-1));
    float kk[4]; int xx[4];
#pragma unroll
    for (int m = 0; m < 4; ++m) { kk[m] = g_key[i0 + m*q]; xx[m] = g_sidx[i0 + m*q]; }
    bool asc = ((i0 & k) == 0);
    ce(kk[0],xx[0],kk[2],xx[2],asc); ce(kk[1],xx[1],kk[3],xx[3],asc);
    ce(kk[0],xx[0],kk[1],xx[1],asc); ce(kk[2],xx[2],kk[3],xx[3],asc);
#pragma unroll
    for (int m = 0; m < 4; ++m) { g_key[i0 + m*q] = kk[m]; g_sidx[i0 + m*q] = xx[m]; }
}

__global__ void k_gp3(int k, int j)
{
    int t = blockIdx.x*blockDim.x + threadIdx.x;   // < MSORT/8
    int q = j >> 2;
    int i0 = ((t & ~(q-1)) << 3) | (t & (q-1));
    float kk[8]; int xx[8];
#pragma unroll
    for (int m = 0; m < 8; ++m) { kk[m] = g_key[i0 + m*q]; xx[m] = g_sidx[i0 + m*q]; }
    bool asc = ((i0 & k) == 0);
#pragma unroll
    for (int m = 0; m < 4; ++m) ce(kk[m],xx[m],kk[m+4],xx[m+4],asc);
    ce(kk[0],xx[0],kk[2],xx[2],asc); ce(kk[1],xx[1],kk[3],xx[3],asc);
    ce(kk[4],xx[4],kk[6],xx[6],asc); ce(kk[5],xx[5],kk[7],xx[7],asc);
    ce(kk[0],xx[0],kk[1],xx[1],asc); ce(kk[2],xx[2],kk[3],xx[3],asc);
    ce(kk[4],xx[4],kk[5],xx[5],asc); ce(kk[6],xx[6],kk[7],xx[7],asc);
#pragma unroll
    for (int m = 0; m < 8; ++m) { g_key[i0 + m*q] = kk[m]; g_sidx[i0 + m*q] = xx[m]; }
}

__global__ void k_mergeshared(int k)
{
    __shared__ float sk[2048];
    __shared__ int   si[2048];
    int t = threadIdx.x;
    int base = blockIdx.x * 2048;
    sk[t]        = g_key[base + t];        si[t]        = g_sidx[base + t];
    sk[t + 1024] = g_key[base + t + 1024]; si[t + 1024] = g_sidx[base + t + 1024];
    bool asc = ((base & k) == 0);
    for (int j = 1024; j > 0; j >>= 1) {
        __syncthreads();
        int i = ((t & ~(j-1)) << 1) | (t & (j-1));
        int p = i + j;
        float ki = sk[i], kp = sk[p];
        int   xi = si[i], xp = si[p];
        if (cmp_gt(ki, xi, kp, xp) == asc) {
            sk[i] = kp; sk[p] = ki; si[i] = xp; si[p] = xi;
        }
    }
    __syncthreads();
    g_key[base + t]        = sk[t];        g_sidx[base + t]        = si[t];
    g_key[base + t + 1024] = sk[t + 1024]; g_sidx[base + t + 1024] = si[t + 1024];
}

// ---------------- conv weight transpose: [co][ci][k] -> [k][ci][co] ----------
__global__ void k_transw(const float* __restrict__ w1, const float* __restrict__ w2)
{
    int t = blockIdx.x*blockDim.x + threadIdx.x;
    if (t >= 2*5*64*64) return;
    int which = t >= 5*64*64;
    int u = t - which*5*64*64;
    int co = u & 63;
    int ci = (u >> 6) & 63;
    int kk = u >> 12;
    float v = which ? w2[co*320 + ci*5 + kk] : w1[co*320 + ci*5 + kk];
    if (which) g_w2t[u] = v; else g_w1t[u] = v;
}

// ---------------- conv1d over ranks (K=5, pad=2, 8x4 microtile) --------------
// 128-row tile + 4-row halo, 256 threads; per-tap weight reload (16KB).
// gather=1: input row r is g_key[r] * g_h1[g_sidx[r]][ci]  (fused buildsx)
__global__ void __launch_bounds__(256) k_conv(
    const float* __restrict__ X, const float* __restrict__ Wt,
    const float* __restrict__ b, float* __restrict__ Y,
    const int* __restrict__ scat, int relu, int gather, int n)
{
    extern __shared__ float cs[];
    float (*xs)[64] = reinterpret_cast<float(*)[64]>(cs);           // [132][64]
    float (*ws)[64] = reinterpret_cast<float(*)[64]>(cs + 132*64);  // [64][64]
    int tx = threadIdx.x;           // 0..15
    int ty = threadIdx.y;           // 0..15
    int tid = ty*16 + tx;
    int r0 = blockIdx.x * 128;
    for (int idx = tid; idx < 132*64; idx += 256) {
        int rl = idx >> 6, ci = idx & 63;
        int r = r0 - 2 + rl;
        float v = 0.f;
        if (r >= 0 && r < n) {
            if (gather) v = g_key[r] * g_h1[(size_t)g_sidx[r]*64 + ci];
            else        v = X[(size_t)r*64 + ci];
        }
        xs[rl][ci] = v;
    }
    u64 acc[8][2] = {};
    for (int k = 0; k < 5; ++k) {
        __syncthreads();
        for (int idx = tid; idx < 4096; idx += 256)
            ws[idx >> 6][idx & 63] = Wt[k*4096 + idx];
        __syncthreads();
#pragma unroll 2
        for (int c4 = 0; c4 < 64; c4 += 4) {
            float4 av[8];
#pragma unroll
            for (int i = 0; i < 8; ++i)
                av[i] = *reinterpret_cast<const float4*>(&xs[ty*8+i+k][c4]);
            const float* af = reinterpret_cast<const float*>(av);
#pragma unroll
            for (int cc = 0; cc < 4; ++cc) {
                ulonglong2 w = *reinterpret_cast<const ulonglong2*>(&ws[c4+cc][tx*4]);
#pragma unroll
                for (int i = 0; i < 8; ++i) {
                    u64 ai = dup2(af[i*4 + cc]);
                    fma2(acc[i][0], ai, w.x); fma2(acc[i][1], ai, w.y);
                }
            }
        }
    }
#pragma unroll
    for (int i = 0; i < 8; ++i) {
        int r = r0 + ty*8 + i;
        if (r < n) {
            int orow = scat ? scat[r] : r;
            float2 lo = up2(acc[i][0]), hi = up2(acc[i][1]);
            float4 o;
            o.x = lo.x + b[tx*4 + 0];
            o.y = lo.y + b[tx*4 + 1];
            o.z = hi.x + b[tx*4 + 2];
            o.w = hi.y + b[tx*4 + 3];
            if (relu) {
                o.x = fmaxf(o.x, 0.f); o.y = fmaxf(o.y, 0.f);
                o.z = fmaxf(o.z, 0.f); o.w = fmaxf(o.w, 0.f);
            }
            *reinterpret_cast<float4*>(&Y[(size_t)orow*64 + tx*4]) = o;
        }
    }
}

// ---------------- final linear: out = [h1|h2] @ lin_w + lin_b ----------------
__global__ void __launch_bounds__(256) k_lin(
    const float* __restrict__ A0, const float* __restrict__ A1,
    const float* __restrict__ W, const float* __restrict__ b,
    float* __restrict__ C, int n)
{
    __shared__ float As[128][64];
    __shared__ float Ws[64][64];
    int tx = threadIdx.x;
    int ty = threadIdx.y;
    int tid = ty*16 + tx;
    int r0 = blockIdx.x * 128;
    u64 acc[8][2] = {};
    for (int kt = 0; kt < 2; ++kt) {
        const float* A = (kt == 0) ? A0 : A1;
        __syncthreads();
        for (int idx = tid; idx < 128*64; idx += 256) {
            int row = idx >> 6, k = idx & 63;
            int gr = r0 + row;
            As[row][k] = (gr < n) ? A[(size_t)gr*64 + k] : 0.f;
        }
        for (int idx = tid; idx < 64*64; idx += 256) {
            int kr = idx >> 6, c = idx & 63;
            Ws[kr][c] = W[(size_t)(kt*64 + kr)*64 + c];
        }
        __syncthreads();
#pragma unroll 2
        for (int k4 = 0; k4 < 64; k4 += 4) {
            float4 av[8];
#pragma unroll
            for (int i = 0; i < 8; ++i)
                av[i] = *reinterpret_cast<const float4*>(&As[ty*8+i][k4]);
            const float* af = reinterpret_cast<const float*>(av);
#pragma unroll
            for (int kk = 0; kk < 4; ++kk) {
                ulonglong2 w = *reinterpret_cast<const ulonglong2*>(&Ws[k4+kk][tx*4]);
#pragma unroll
                for (int i = 0; i < 8; ++i) {
                    u64 ai = dup2(af[i*4 + kk]);
                    fma2(acc[i][0], ai, w.x); fma2(acc[i][1], ai, w.y);
                }
            }
        }
    }
#pragma unroll
    for (int i = 0; i < 8; ++i) {
        int gr = r0 + ty*8 + i;
        if (gr < n) {
            float2 lo = up2(acc[i][0]), hi = up2(acc[i][1]);
            float4 o;
            o.x = lo.x + b[tx*4 + 0];
            o.y = lo.y + b[tx*4 + 1];
            o.z = hi.x + b[tx*4 + 2];
            o.w = hi.y + b[tx*4 + 3];
            *reinterpret_cast<float4*>(&C[(size_t)gr*64 + tx*4]) = o;
        }
    }
}

// ---------------- host launcher ---------------------------------------------
extern "C" void kernel_launch(void* const* d_in, const int* in_sizes, int n_in,
                              void* d_out, int out_size)
{
    const float* x   = (const float*)d_in[0];
    const int*   ei  = (const int*)  d_in[1];
    const float* W0  = (const float*)d_in[2];
    const float* b0  = (const float*)d_in[3];
    const float* W1  = (const float*)d_in[4];
    const float* b1  = (const float*)d_in[5];
    const float* W2  = (const float*)d_in[6];
    const float* b2  = (const float*)d_in[7];
    const float* Wp  = (const float*)d_in[8];
    const float* bp  = (const float*)d_in[9];
    const float* c1w = (const float*)d_in[10];
    const float* c1b = (const float*)d_in[11];
    const float* c2w = (const float*)d_in[12];
    const float* c2b = (const float*)d_in[13];
    const float* lw  = (const float*)d_in[14];
    const float* lb  = (const float*)d_in[15];
    float* out = (float*)d_out;

    const int n = NN, E = NE;
    const int* src = ei;
    const int* dst = ei + E;

    float *p_tmp, *p_bufA, *p_bufB, *p_h1, *p_h2, *p_c1, *p_w1t, *p_w2t;
    int *p_sidx;
    cudaGetSymbolAddress((void**)&p_tmp,  g_tmp);
    cudaGetSymbolAddress((void**)&p_bufA, g_bufA);
    cudaGetSymbolAddress((void**)&p_bufB, g_bufB);
    cudaGetSymbolAddress((void**)&p_h1,   g_h1);
    cudaGetSymbolAddress((void**)&p_h2,   g_h2);
    cudaGetSymbolAddress((void**)&p_c1,   g_c1);
    cudaGetSymbolAddress((void**)&p_w1t,  g_w1t);
    cudaGetSymbolAddress((void**)&p_w2t,  g_w2t);
    cudaGetSymbolAddress((void**)&p_sidx, g_sidx);

    const int CONV_SMEM = (132*64 + 64*64) * 4;   // 50,176 B
    cudaFuncSetAttribute(k_conv, cudaFuncAttributeMaxDynamicSharedMemorySize, CONV_SMEM);

    dim3 tg(16, 16);
    int  gb  = (n + 127) / 128;
    int  ab  = (n + 7) / 8;     // warp per node, 8 warps/block

    // ---- CSR build; layer-0 gemm kept as 4th launch (stable ncu slot) ----
    k_init <<<(MSORT + 255)/256, 256>>>();
    k_deg  <<<(E + 255)/256, 256>>>(dst);
    k_scan1<<<NB, SCB>>>();
    k_gemm <<<gb, tg>>>(x, 128, W0, p_tmp, n);          // <-- profile target
    k_scan2<<<1, 128>>>();
    k_scan3<<<NB, SCB>>>();
    k_fill <<<(E + 255)/256, 256>>>(src, dst);

    // ---- 3 GCN layers (layer 3 fuses the score projection) ----
    k_agg <<<ab, 256>>>(p_tmp, b0, p_bufA, 1, n, nullptr, nullptr);
    k_gemm<<<gb, tg>>>(p_bufA, 64, W1, p_tmp, n);
    k_agg <<<ab, 256>>>(p_tmp, b1, p_bufB, 1, n, nullptr, nullptr);
    k_gemm<<<gb, tg>>>(p_bufB, 64, W2, p_tmp, n);
    k_agg <<<ab, 256>>>(p_tmp, b2, p_h1, 0, n, Wp, bp);

    // ---- stable bitonic argsort (fused global steps) ----
    k_localsort<<<MSORT/2048, 1024>>>();
    for (int k = 4096; k <= MSORT; k <<= 1) {
        int j = k >> 1;
        while (j >= 2048) {
            if (j >= 8192)      { k_gp3<<<MSORT/8/256, 256>>>(k, j); j >>= 3; }
            else if (j >= 4096) { k_gp2<<<MSORT/4/256, 256>>>(k, j); j >>= 2; }
            else                { k_gp1<<<MSORT/2/256, 256>>>(k, j); j >>= 1; }
        }
        k_mergeshared<<<MSORT/2048, 1024>>>(k);
    }

    // ---- convs (conv1 gathers sorted_x on the fly, conv2 scatters back),
    //      final linear ----
    k_transw<<<(2*5*64*64 + 255)/256, 256>>>(c1w, c2w);
    k_conv<<<gb, tg, CONV_SMEM>>>(nullptr, p_w1t, c1b, p_c1, nullptr, 1, 1, n);
    k_conv<<<gb, tg, CONV_SMEM>>>(p_c1,    p_w2t, c2b, p_h2, p_sidx, 0, 0, n);
    k_lin<<<gb, tg>>>(p_h1, p_h2, lw, lb, out, n);
}